// round 5
// baseline (speedup 1.0000x reference)
#include <cuda_runtime.h>

// Problem constants (fixed shapes for this dataset)
#define L_  50      // components per sample
#define D_  50      // feat dim
#define R_  3       // rows per combo
#define C_  10      // combos per sample
#define VOCAB_ 100000
#define WARPS_PER_BLOCK 8

// Scratch: P[v] = (dot(table[v],W0), dot(table[v],W1), dot(table[v],W2), 0)
// float4-padded so each gather is one 16B load. 1.6 MB, L2-resident.
__device__ float4 g_P[VOCAB_];

// Half-warp (16-lane) butterfly reduction: valid within each 16-lane group.
__device__ __forceinline__ float half_reduce_add(float v) {
    v += __shfl_xor_sync(0xFFFFFFFFu, v, 1);
    v += __shfl_xor_sync(0xFFFFFFFFu, v, 2);
    v += __shfl_xor_sync(0xFFFFFFFFu, v, 4);
    v += __shfl_xor_sync(0xFFFFFFFFu, v, 8);
    return v;
}

// Full-warp butterfly reduction.
__device__ __forceinline__ float warp_reduce_add(float v) {
    v += __shfl_xor_sync(0xFFFFFFFFu, v, 16);
    v += __shfl_xor_sync(0xFFFFFFFFu, v, 8);
    v += __shfl_xor_sync(0xFFFFFFFFu, v, 4);
    v += __shfl_xor_sync(0xFFFFFFFFu, v, 2);
    v += __shfl_xor_sync(0xFFFFFFFFu, v, 1);
    return v;
}

// ---------------------------------------------------------------------------
// Kernel 1: P[v][r] = dot(table[v], W[r]) for all v. 16 lanes per row, two
// rows per warp (halves). Lane h owns feature slots 2h..2h+1 and 2(h+16)..+1.
// Streams the 20 MB table exactly once, coalesced.
// ---------------------------------------------------------------------------
__global__ void __launch_bounds__(256)
precompute_P_kernel(const float* __restrict__ table,
                    const float* __restrict__ W)
{
    const int lane = threadIdx.x & 31;
    const int wg   = (blockIdx.x * blockDim.x + threadIdx.x) >> 5;
    const int half = lane >> 4;
    const int h    = lane & 15;

    const int v = wg * 2 + half;          // both halves exit together
    if (v >= VOCAB_) return;

    // W coefficients for this lane's feature slots (L1-resident after warmup)
    float2 w0a = *(const float2*)(W + 0 * D_ + 2 * h);
    float2 w1a = *(const float2*)(W + 1 * D_ + 2 * h);
    float2 w2a = *(const float2*)(W + 2 * D_ + 2 * h);
    const bool has2 = (h < 9);            // second slot d2 = h+16 valid for h<=8
    float2 w0b = make_float2(0.f, 0.f), w1b = w0b, w2b = w0b;
    if (has2) {
        w0b = *(const float2*)(W + 0 * D_ + 2 * (h + 16));
        w1b = *(const float2*)(W + 1 * D_ + 2 * (h + 16));
        w2b = *(const float2*)(W + 2 * D_ + 2 * (h + 16));
    }

    const float* row = table + v * D_;    // 200B stride, 8B aligned
    float2 e0 = *(const float2*)(row + 2 * h);
    float a0 = e0.x * w0a.x + e0.y * w0a.y;
    float a1 = e0.x * w1a.x + e0.y * w1a.y;
    float a2 = e0.x * w2a.x + e0.y * w2a.y;
    if (has2) {
        float2 e1 = *(const float2*)(row + 32 + 2 * h);
        a0 = fmaf(e1.x, w0b.x, fmaf(e1.y, w0b.y, a0));
        a1 = fmaf(e1.x, w1b.x, fmaf(e1.y, w1b.y, a1));
        a2 = fmaf(e1.x, w2b.x, fmaf(e1.y, w2b.y, a2));
    }

    // 16-lane butterfly reductions (stay within each half-warp)
    a0 = half_reduce_add(a0);
    a1 = half_reduce_add(a1);
    a2 = half_reduce_add(a2);

    if (h == 0)
        g_P[v] = make_float4(a0, a1, a2, 0.f);
}

// ---------------------------------------------------------------------------
// Kernel 2: one warp per sample. Lane l (and l+32 for lane<18) handles one
// component: gather P[x[b,l]] (one 16B load), scale by mask, stash in shared.
// Then lanes 0..9 evaluate the 10 combos + sigmoid, full-warp reduce, store.
//
// Index dtype is detected at runtime (warp-uniform): probe the first 16 odd
// word positions of each index buffer — always in-bounds under either
// interpretation. int64 data has all hi-words == 0; int32 data fails the
// probe with overwhelming probability (values are uniform in [0,VOCAB) /
// [0,L)). The resulting stride (2 or 1 words) is uniform across the grid
// and deterministic for fixed inputs.
// ---------------------------------------------------------------------------
__global__ void __launch_bounds__(32 * WARPS_PER_BLOCK)
score_combo_kernel(
    const int*   __restrict__ xw,     // x buffer viewed as 32-bit words
    const float* __restrict__ mask,   // [B, L]
    const int*   __restrict__ cw,     // combo_idx buffer viewed as 32-bit words
    const float* __restrict__ bias,   // [1]
    float*       __restrict__ out,    // [B]
    int B)
{
    __shared__ float4 s4[WARPS_PER_BLOCK][L_];   // per-sample scaled scores

    const int warp = threadIdx.x >> 5;
    const int lane = threadIdx.x & 31;
    const int b = blockIdx.x * WARPS_PER_BLOCK + warp;
    if (b >= B) return;

    // ---- dtype probes (broadcast addresses; L1-hit after first warp) ----
    bool zx = true, zc = true;
    if (lane < 16) {
        zx = (__ldg(xw + 2 * lane + 1) == 0);
        zc = (__ldg(cw + 2 * lane + 1) == 0);
    }
    const int xs = __all_sync(0xFFFFFFFFu, zx) ? 2 : 1;  // word stride of x
    const int cs = __all_sync(0xFFFFFFFFu, zc) ? 2 : 1;  // word stride of combo

    const int xbase = b * L_;

    // Prefetch combo indices (hidden under the gathers below)
    int i0 = 0, i1 = 0, i2 = 0;
    if (lane < C_) {
        const int* ci = cw + cs * (b * (C_ * R_) + lane * R_);
        i0 = __ldg(ci);
        i1 = __ldg(ci + cs);
        i2 = __ldg(ci + 2 * cs);
    }
    const float bias0 = __ldg(bias);

    // Component l = lane
    {
        const int   idx = __ldg(xw + xs * (xbase + lane));
        const float m   = __ldg(mask + xbase + lane);
        const float4 p  = g_P[idx];
        s4[warp][lane] = make_float4(p.x * m, p.y * m, p.z * m, 0.f);
    }
    // Component l = lane + 32 (only lanes 0..17)
    if (lane < L_ - 32) {
        const int   l   = lane + 32;
        const int   idx = __ldg(xw + xs * (xbase + l));
        const float m   = __ldg(mask + xbase + l);
        const float4 p  = g_P[idx];
        s4[warp][l] = make_float4(p.x * m, p.y * m, p.z * m, 0.f);
    }
    __syncwarp();

    float acc = 0.f;
    if (lane < C_) {
        const float t = s4[warp][i0].x + s4[warp][i1].y + s4[warp][i2].z + bias0;
        acc = 1.f / (1.f + __expf(-t));
    }
    acc = warp_reduce_add(acc);
    if (lane == 0) out[b] = acc;
}

extern "C" void kernel_launch(void* const* d_in, const int* in_sizes, int n_in,
                              void* d_out, int out_size)
{
    const int B = out_size;   // OUT == 1, so out elements == batch

    // Positional mapping per reference signature order:
    //   x, emb_mask, combo_idx, [step], emb_table, W, b
    // Works whether or not the scalar `step` is materialized as an input:
    // the first three and last three positions are invariant.
    const void* px = d_in[0];
    const void* pm = d_in[1];
    const void* pc = d_in[2];
    const void* pt = d_in[n_in - 3];
    const void* pw = d_in[n_in - 2];
    const void* pb = d_in[n_in - 1];

    // Sanity overlay: table and W are unambiguous by size; prefer size match
    // if positional slots look wrong.
    if (in_sizes[n_in - 3] != VOCAB_ * D_ || in_sizes[n_in - 2] != R_ * D_) {
        for (int i = 0; i < n_in; ++i) {
            const long s = (long)in_sizes[i];
            if (s == (long)VOCAB_ * D_) pt = d_in[i];
            else if (s == (long)R_ * D_) pw = d_in[i];
        }
    }

    // Kernel 1: precompute P (same stream -> ordered before kernel 2)
    {
        const int warps_needed = (VOCAB_ + 1) / 2;           // 2 rows per warp
        const int blocks = (warps_needed + 7) / 8;           // 8 warps/block
        precompute_P_kernel<<<blocks, 256>>>((const float*)pt, (const float*)pw);
    }

    // Kernel 2: scores + combos + sigmoid + sum
    {
        const int grid = (B + WARPS_PER_BLOCK - 1) / WARPS_PER_BLOCK;
        score_combo_kernel<<<grid, 32 * WARPS_PER_BLOCK>>>(
            (const int*)px, (const float*)pm, (const int*)pc,
            (const float*)pb, (float*)d_out, B);
    }
}

// round 17
// speedup vs baseline: 1.2299x; 1.2299x over previous
#include <cuda_runtime.h>

// Problem constants (fixed shapes for this dataset)
#define L_  50      // components per sample
#define D_  50      // feat dim
#define R_  3       // rows per combo
#define C_  10      // combos per sample
#define VOCAB_ 100000
#define WARPS_PER_BLOCK 8

// Scratch: three scalar planes P_r[v] = dot(table[v], W[r]).
// 400 KB each, 1.2 MB total -> L2-resident, partially L1-resident.
__device__ float g_P0[VOCAB_];
__device__ float g_P1[VOCAB_];
__device__ float g_P2[VOCAB_];

// Half-warp (16-lane) butterfly reduction: valid within each 16-lane group.
__device__ __forceinline__ float half_reduce_add(float v) {
    v += __shfl_xor_sync(0xFFFFFFFFu, v, 1);
    v += __shfl_xor_sync(0xFFFFFFFFu, v, 2);
    v += __shfl_xor_sync(0xFFFFFFFFu, v, 4);
    v += __shfl_xor_sync(0xFFFFFFFFu, v, 8);
    return v;
}

// Full-warp butterfly reduction.
__device__ __forceinline__ float warp_reduce_add(float v) {
    v += __shfl_xor_sync(0xFFFFFFFFu, v, 16);
    v += __shfl_xor_sync(0xFFFFFFFFu, v, 8);
    v += __shfl_xor_sync(0xFFFFFFFFu, v, 4);
    v += __shfl_xor_sync(0xFFFFFFFFu, v, 2);
    v += __shfl_xor_sync(0xFFFFFFFFu, v, 1);
    return v;
}

// ---------------------------------------------------------------------------
// Kernel 1: P_r[v] = dot(table[v], W[r]) for all v.
// 16 lanes per row, 4 rows per warp (two row-pairs, loads batched up front
// for MLP=4-6). Streams the 20 MB table exactly once.
// ---------------------------------------------------------------------------
__global__ void __launch_bounds__(256)
precompute_P_kernel(const float* __restrict__ table,
                    const float* __restrict__ W)
{
    const int lane = threadIdx.x & 31;
    const int wg   = (blockIdx.x * blockDim.x + threadIdx.x) >> 5;
    const int half = lane >> 4;
    const int h    = lane & 15;

    const int v0 = wg * 4 + half;         // rows v0 and v0+2 (VOCAB_ % 4 == 0)
    if (v0 >= VOCAB_) return;
    const int v1 = v0 + 2;

    // W coefficients for this lane's feature slots (L1-resident after warmup)
    float2 w0a = *(const float2*)(W + 0 * D_ + 2 * h);
    float2 w1a = *(const float2*)(W + 1 * D_ + 2 * h);
    float2 w2a = *(const float2*)(W + 2 * D_ + 2 * h);
    const bool has2 = (h < 9);            // second slot d2 = h+16 valid for h<=8
    float2 w0b = make_float2(0.f, 0.f), w1b = w0b, w2b = w0b;
    if (has2) {
        w0b = *(const float2*)(W + 0 * D_ + 2 * (h + 16));
        w1b = *(const float2*)(W + 1 * D_ + 2 * (h + 16));
        w2b = *(const float2*)(W + 2 * D_ + 2 * (h + 16));
    }

    const float* r0 = table + v0 * D_;    // 200B stride, 8B aligned
    const float* r1 = table + v1 * D_;

    // Batch all global loads first (4-6 outstanding)
    float2 e0a = *(const float2*)(r0 + 2 * h);
    float2 e1a = *(const float2*)(r1 + 2 * h);
    float2 e0b = make_float2(0.f, 0.f), e1b = e0b;
    if (has2) {
        e0b = *(const float2*)(r0 + 32 + 2 * h);
        e1b = *(const float2*)(r1 + 32 + 2 * h);
    }

    float a0 = e0a.x * w0a.x + e0a.y * w0a.y;
    float a1 = e0a.x * w1a.x + e0a.y * w1a.y;
    float a2 = e0a.x * w2a.x + e0a.y * w2a.y;
    float b0 = e1a.x * w0a.x + e1a.y * w0a.y;
    float b1 = e1a.x * w1a.x + e1a.y * w1a.y;
    float b2 = e1a.x * w2a.x + e1a.y * w2a.y;
    if (has2) {
        a0 = fmaf(e0b.x, w0b.x, fmaf(e0b.y, w0b.y, a0));
        a1 = fmaf(e0b.x, w1b.x, fmaf(e0b.y, w1b.y, a1));
        a2 = fmaf(e0b.x, w2b.x, fmaf(e0b.y, w2b.y, a2));
        b0 = fmaf(e1b.x, w0b.x, fmaf(e1b.y, w0b.y, b0));
        b1 = fmaf(e1b.x, w1b.x, fmaf(e1b.y, w1b.y, b1));
        b2 = fmaf(e1b.x, w2b.x, fmaf(e1b.y, w2b.y, b2));
    }

    // Six independent 16-lane butterfly reductions (pipelined shfls)
    a0 = half_reduce_add(a0);
    a1 = half_reduce_add(a1);
    a2 = half_reduce_add(a2);
    b0 = half_reduce_add(b0);
    b1 = half_reduce_add(b1);
    b2 = half_reduce_add(b2);

    if (h == 0) {
        g_P0[v0] = a0; g_P1[v0] = a1; g_P2[v0] = a2;
        g_P0[v1] = b0; g_P1[v1] = b1; g_P2[v1] = b2;
    }
}

// ---------------------------------------------------------------------------
// Kernel 2: TWO samples per warp (b0 = 2w, b1 = 2w+1); only the C*R = 30
// referenced (l, r) pairs per sample are computed. Per sample: lanes 0..24
// load x (int4 = 2 int64 indices) + mask (float2) coalesced; lanes 0..29
// load their combo element l; x/mask routed to combo lanes via register
// shuffle; each combo lane gathers ONE scalar per sample from plane P_r
// (two independent gathers/lane -> MLP 2 on the random path). 3-lane shfl
// sums -> sigmoid on 10 lanes -> warp sum per sample -> one float2 store.
//
// Index dtype detected at runtime (warp-uniform probe of odd word positions;
// always in-bounds under either interpretation, false-positive prob ~0).
// ---------------------------------------------------------------------------
__global__ void __launch_bounds__(32 * WARPS_PER_BLOCK)
score_combo_kernel(
    const int*   __restrict__ xw,     // x buffer viewed as 32-bit words
    const float* __restrict__ mask,   // [B, L]
    const int*   __restrict__ cw,     // combo_idx buffer viewed as 32-bit words
    const float* __restrict__ bias,   // [1]
    float*       __restrict__ out,    // [B]
    int B)
{
    const int warp = threadIdx.x >> 5;
    const int lane = threadIdx.x & 31;
    const int w  = blockIdx.x * WARPS_PER_BLOCK + warp;
    const int b0 = 2 * w;
    if (b0 >= B) return;
    const int b1 = b0 + 1;                // B = 32768 is even; b1 always valid

    // ---- dtype probes (broadcast addresses; L1-hit after first warp) ----
    bool zx = true, zc = true;
    if (lane < 16) {
        zx = (__ldg(xw + 2 * lane + 1) == 0);
        zc = (__ldg(cw + 2 * lane + 1) == 0);
    }
    const int xs = __all_sync(0xFFFFFFFFu, zx) ? 2 : 1;  // word stride of x
    const int cs = __all_sync(0xFFFFFFFFu, zc) ? 2 : 1;  // word stride of combo

    const int xbase0 = b0 * L_;
    const int xbase1 = b1 * L_;

    // ---- issue all independent loads up front (max front-batch MLP) ----
    const float bias0 = __ldg(bias);

    // combo elements: lane e -> (c = e/3, r = e%3), one per sample
    int lA = 0, lB = 0;
    if (lane < C_ * R_) {
        lA = __ldg(cw + cs * (b0 * (C_ * R_) + lane));
        lB = __ldg(cw + cs * (b1 * (C_ * R_) + lane));
    }

    // x + mask, two components per lane per sample (lanes 0..24)
    int   ia0 = 0, ib0 = 0, ia1 = 0, ib1 = 0;
    float ma0 = 0.f, mb0 = 0.f, ma1 = 0.f, mb1 = 0.f;
    if (lane < L_ / 2) {
        if (xs == 2) {
            // int64 indices: one 16B load = two indices (byte addr 400*b + 16*lane)
            const int4 tA = __ldg((const int4*)(xw + 2 * xbase0 + 4 * lane));
            const int4 tB = __ldg((const int4*)(xw + 2 * xbase1 + 4 * lane));
            ia0 = tA.x; ib0 = tA.z;
            ia1 = tB.x; ib1 = tB.z;
        } else {
            const int2 tA = __ldg((const int2*)(xw + xbase0 + 2 * lane));
            const int2 tB = __ldg((const int2*)(xw + xbase1 + 2 * lane));
            ia0 = tA.x; ib0 = tA.y;
            ia1 = tB.x; ib1 = tB.y;
        }
        const float2 mA = __ldg((const float2*)(mask + xbase0 + 2 * lane));
        const float2 mB = __ldg((const float2*)(mask + xbase1 + 2 * lane));
        ma0 = mA.x; mb0 = mA.y;
        ma1 = mB.x; mb1 = mB.y;
    }

    // ---- route x[l] and mask[l] to combo lanes via shuffles ----
    const int srcA = lA >> 1;             // holding lane (0..24)
    const int srcB = lB >> 1;
    const int   vaA = __shfl_sync(0xFFFFFFFFu, ia0, srcA);
    const int   vbA = __shfl_sync(0xFFFFFFFFu, ib0, srcA);
    const float faA = __shfl_sync(0xFFFFFFFFu, ma0, srcA);
    const float fbA = __shfl_sync(0xFFFFFFFFu, mb0, srcA);
    const int   vaB = __shfl_sync(0xFFFFFFFFu, ia1, srcB);
    const int   vbB = __shfl_sync(0xFFFFFFFFu, ib1, srcB);
    const float faB = __shfl_sync(0xFFFFFFFFu, ma1, srcB);
    const float fbB = __shfl_sync(0xFFFFFFFFu, mb1, srcB);
    const int   xvA = (lA & 1) ? vbA : vaA;
    const float mvA = (lA & 1) ? fbA : faA;
    const int   xvB = (lB & 1) ? vbB : vaB;
    const float mvB = (lB & 1) ? fbB : faB;

    // ---- two independent scalar gathers from the r-th plane ----
    const int c3 = lane / 3;
    const int r  = lane - 3 * c3;
    float valA = 0.f, valB = 0.f;
    if (lane < C_ * R_) {
        const float* plane = (r == 0) ? g_P0 : (r == 1) ? g_P1 : g_P2;
        valA = __ldg(plane + xvA) * mvA;
        valB = __ldg(plane + xvB) * mvB;
    }

    // ---- sum the 3 elements of each combo (lanes r==0 collect) ----
    const float a1v = __shfl_down_sync(0xFFFFFFFFu, valA, 1);
    const float a2v = __shfl_down_sync(0xFFFFFFFFu, valA, 2);
    const float b1v = __shfl_down_sync(0xFFFFFFFFu, valB, 1);
    const float b2v = __shfl_down_sync(0xFFFFFFFFu, valB, 2);

    float accA = 0.f, accB = 0.f;
    if (lane < C_ * R_ && r == 0) {
        const float tA = valA + a1v + a2v + bias0;
        const float tB = valB + b1v + b2v + bias0;
        accA = 1.f / (1.f + __expf(-tA));
        accB = 1.f / (1.f + __expf(-tB));
    }
    accA = warp_reduce_add(accA);
    accB = warp_reduce_add(accB);
    if (lane == 0)
        *(float2*)(out + b0) = make_float2(accA, accB);   // b0 even -> 8B aligned
}

extern "C" void kernel_launch(void* const* d_in, const int* in_sizes, int n_in,
                              void* d_out, int out_size)
{
    const int B = out_size;   // OUT == 1, so out elements == batch

    // Positional mapping per reference signature order:
    //   x, emb_mask, combo_idx, [step], emb_table, W, b
    const void* px = d_in[0];
    const void* pm = d_in[1];
    const void* pc = d_in[2];
    const void* pt = d_in[n_in - 3];
    const void* pw = d_in[n_in - 2];
    const void* pb = d_in[n_in - 1];

    // Sanity overlay: table and W are unambiguous by size.
    if (in_sizes[n_in - 3] != VOCAB_ * D_ || in_sizes[n_in - 2] != R_ * D_) {
        for (int i = 0; i < n_in; ++i) {
            const long s = (long)in_sizes[i];
            if (s == (long)VOCAB_ * D_) pt = d_in[i];
            else if (s == (long)R_ * D_) pw = d_in[i];
        }
    }

    // Kernel 1: precompute P planes (same stream -> ordered before kernel 2)
    {
        const int warps_needed = (VOCAB_ + 3) / 4;           // 4 rows per warp
        const int blocks = (warps_needed + 7) / 8;           // 8 warps/block
        precompute_P_kernel<<<blocks, 256>>>((const float*)pt, (const float*)pw);
    }

    // Kernel 2: combo-only scores + sigmoid + sum, 2 samples per warp
    {
        const int warps = (B + 1) / 2;
        const int grid  = (warps + WARPS_PER_BLOCK - 1) / WARPS_PER_BLOCK;
        score_combo_kernel<<<grid, 32 * WARPS_PER_BLOCK>>>(
            (const int*)px, (const float*)pm, (const int*)pc,
            (const float*)pb, (float*)d_out, B);
    }
}